// round 3
// baseline (speedup 1.0000x reference)
#include <cuda_runtime.h>
#include <cuda_bf16.h>
#include <cstdint>

#define N_NODES 100000
#define N_EDGES 1600000
#define D_IN    256
#define D_OUT   128

// Scratch (__device__ globals per allocation rules)
__device__ float g_h[(size_t)N_NODES * D_OUT];   // h = x @ W^T + b
__device__ int   g_src[N_EDGES];
__device__ int   g_dst[N_EDGES];

// ---------------------------------------------------------------------------
// Kernel 0: normalize index arrays to int32, auto-detecting int64 vs int32.
// int64 LE viewed as int32 is [val,0,val,0,...]: every odd 32-bit word is 0
// (indices < 100000 are nonnegative 17-bit values). Sample 32 odd words
// spread across the buffer; all-zero => int64. For genuine int32 index data
// the sampled words are random indices (P[all zero] ~ (1e-5)^32).
// ---------------------------------------------------------------------------
__global__ void convert_idx(const int* __restrict__ raw, int* __restrict__ out)
{
    __shared__ int s_is64;
    if (threadIdx.x == 0) {
        int is64 = 1;
        #pragma unroll
        for (int i = 0; i < 32; i++) {
            // spread sample positions across the first half of the int32 view
            long long p = (long long)i * (N_EDGES / 64) * 2 + 1;
            if (raw[p] != 0) { is64 = 0; break; }
        }
        s_is64 = is64;
    }
    __syncthreads();
    const int is64 = s_is64;

    int i = blockIdx.x * blockDim.x + threadIdx.x;
    if (i < N_EDGES) {
        int v = is64 ? raw[2 * i] : raw[i];
        // clamp defensively: wrong values then fail rel-err, not crash
        v = min(max(v, 0), N_NODES - 1);
        out[i] = v;
    }
}

// ---------------------------------------------------------------------------
// Kernel 1: SGEMM  h[m][n] = sum_k x[m][k] * W[n][k] + b[n]
// BM=128, BN=128, BK=16, 256 threads, 8x8 register tile, double-buffered smem.
// ---------------------------------------------------------------------------
__global__ __launch_bounds__(256, 2)
void gemm_xWT_bias(const float* __restrict__ x,
                   const float* __restrict__ W,
                   const float* __restrict__ b,
                   float* __restrict__ h)
{
    __shared__ float As[2][16][128];   // [k][m]
    __shared__ float Bs[2][16][128];   // [k][n]

    const int tid = threadIdx.x;
    const int m0  = blockIdx.x * 128;
    const int tx  = tid & 15;          // n-tile coordinate (8 cols each)
    const int ty  = tid >> 4;          // m-tile coordinate (8 rows each)

    float acc[8][8];
    #pragma unroll
    for (int i = 0; i < 8; i++)
        #pragma unroll
        for (int j = 0; j < 8; j++) acc[i][j] = 0.f;

    float4 pa[2], pb[2];

    auto ldg_chunk = [&](int kc) {
        #pragma unroll
        for (int i = 0; i < 2; i++) {
            int idx = tid + i * 256;
            int r   = idx >> 2;        // 0..127
            int c4  = idx & 3;         // 0..3 (k group of 4)
            int gr  = m0 + r;
            if (gr >= N_NODES) gr = N_NODES - 1;   // clamp; masked on store
            pa[i] = *(const float4*)&x[(size_t)gr * D_IN + kc * 16 + c4 * 4];
            pb[i] = *(const float4*)&W[(size_t)r  * D_IN + kc * 16 + c4 * 4];
        }
    };
    auto sts_chunk = [&](int buf) {
        #pragma unroll
        for (int i = 0; i < 2; i++) {
            int idx = tid + i * 256;
            int r   = idx >> 2;
            int c4  = idx & 3;
            As[buf][c4 * 4 + 0][r] = pa[i].x;
            As[buf][c4 * 4 + 1][r] = pa[i].y;
            As[buf][c4 * 4 + 2][r] = pa[i].z;
            As[buf][c4 * 4 + 3][r] = pa[i].w;
            Bs[buf][c4 * 4 + 0][r] = pb[i].x;
            Bs[buf][c4 * 4 + 1][r] = pb[i].y;
            Bs[buf][c4 * 4 + 2][r] = pb[i].z;
            Bs[buf][c4 * 4 + 3][r] = pb[i].w;
        }
    };

    int buf = 0;
    ldg_chunk(0);
    sts_chunk(0);
    __syncthreads();

    const int NCHUNK = D_IN / 16;   // 16
    for (int kc = 0; kc < NCHUNK; kc++) {
        if (kc + 1 < NCHUNK) ldg_chunk(kc + 1);

        #pragma unroll
        for (int k = 0; k < 16; k++) {
            float a[8], bb[8];
            *(float4*)&a[0]  = *(const float4*)&As[buf][k][ty * 8 + 0];
            *(float4*)&a[4]  = *(const float4*)&As[buf][k][ty * 8 + 4];
            *(float4*)&bb[0] = *(const float4*)&Bs[buf][k][tx * 8 + 0];
            *(float4*)&bb[4] = *(const float4*)&Bs[buf][k][tx * 8 + 4];
            #pragma unroll
            for (int i = 0; i < 8; i++)
                #pragma unroll
                for (int j = 0; j < 8; j++)
                    acc[i][j] = fmaf(a[i], bb[j], acc[i][j]);
        }

        if (kc + 1 < NCHUNK) {
            sts_chunk(buf ^ 1);
            __syncthreads();
            buf ^= 1;
        }
    }

    float bv[8];
    *(float4*)&bv[0] = *(const float4*)&b[tx * 8 + 0];
    *(float4*)&bv[4] = *(const float4*)&b[tx * 8 + 4];

    #pragma unroll
    for (int i = 0; i < 8; i++) {
        int row = m0 + ty * 8 + i;
        if (row < N_NODES) {
            float4 o0, o1;
            o0.x = acc[i][0] + bv[0]; o0.y = acc[i][1] + bv[1];
            o0.z = acc[i][2] + bv[2]; o0.w = acc[i][3] + bv[3];
            o1.x = acc[i][4] + bv[4]; o1.y = acc[i][5] + bv[5];
            o1.z = acc[i][6] + bv[6]; o1.w = acc[i][7] + bv[7];
            *(float4*)&h[(size_t)row * D_OUT + tx * 8 + 0] = o0;
            *(float4*)&h[(size_t)row * D_OUT + tx * 8 + 4] = o1;
        }
    }
}

// ---------------------------------------------------------------------------
// Kernel 2: zero the output (harness poisons d_out with 0xAA)
// ---------------------------------------------------------------------------
__global__ void zero_out(float4* __restrict__ out, int n4)
{
    int i = blockIdx.x * blockDim.x + threadIdx.x;
    if (i < n4) out[i] = make_float4(0.f, 0.f, 0.f, 0.f);
}

// ---------------------------------------------------------------------------
// Kernel 3: edge gather + segment-sum scatter.
// dst is sorted; each block owns a contiguous edge range, each thread owns one
// output channel, accumulates per dst-segment in a register, flushes with
// atomicAdd (only boundaries can collide across blocks).
// ---------------------------------------------------------------------------
#define EPB 256   // edges per block

__global__ __launch_bounds__(128)
void edge_scatter(const int* __restrict__ src,
                  const int* __restrict__ dst,
                  const float* __restrict__ w,
                  const float* __restrict__ h,
                  float* __restrict__ out)
{
    __shared__ int   s_src[EPB];
    __shared__ int   s_dst[EPB];
    __shared__ float s_w[EPB];

    const int e0 = blockIdx.x * EPB;
    if (e0 >= N_EDGES) return;
    const int cnt = min(EPB, N_EDGES - e0);
    const int tid = threadIdx.x;

    for (int i = tid; i < cnt; i += 128) {
        s_src[i] = src[e0 + i];
        s_dst[i] = dst[e0 + i];
        s_w[i]   = w[e0 + i];
    }
    __syncthreads();

    const int c = tid;              // channel 0..127
    float acc = 0.f;
    int cur = s_dst[0];

    for (int j = 0; j < cnt; j++) {
        int d = s_dst[j];
        if (d != cur) {
            atomicAdd(&out[(size_t)cur * D_OUT + c], acc);
            acc = 0.f;
            cur = d;
        }
        acc = fmaf(s_w[j], __ldg(&h[(size_t)s_src[j] * D_OUT + c]), acc);
    }
    atomicAdd(&out[(size_t)cur * D_OUT + c], acc);
}

// ---------------------------------------------------------------------------
// launch
// ---------------------------------------------------------------------------
extern "C" void kernel_launch(void* const* d_in, const int* in_sizes, int n_in,
                              void* d_out, int out_size)
{
    const float* x    = (const float*)d_in[0];
    const int*   srcR = (const int*)d_in[1];
    const int*   dstR = (const int*)d_in[2];
    const float* w    = (const float*)d_in[3];
    const float* W    = (const float*)d_in[4];
    const float* b    = (const float*)d_in[5];
    float*       out  = (float*)d_out;

    float* h = nullptr;
    int *srcI = nullptr, *dstI = nullptr;
    cudaGetSymbolAddress((void**)&h, g_h);
    cudaGetSymbolAddress((void**)&srcI, g_src);
    cudaGetSymbolAddress((void**)&dstI, g_dst);

    // normalize index dtypes (int64-or-int32 -> int32)
    convert_idx<<<(N_EDGES + 255) / 256, 256>>>(srcR, srcI);
    convert_idx<<<(N_EDGES + 255) / 256, 256>>>(dstR, dstI);

    // GEMM: h = x @ W^T + b
    gemm_xWT_bias<<<(N_NODES + 127) / 128, 256>>>(x, W, b, h);

    // zero output
    int n4 = (N_NODES * D_OUT) / 4;
    zero_out<<<(n4 + 255) / 256, 256>>>((float4*)out, n4);

    // scatter
    edge_scatter<<<(N_EDGES + EPB - 1) / EPB, 128>>>(srcI, dstI, w, h, out);
}

// round 5
// speedup vs baseline: 1.2422x; 1.2422x over previous
#include <cuda_runtime.h>
#include <cuda_bf16.h>
#include <cstdint>

#define N_NODES 100000
#define N_EDGES 1600000
#define D_IN    256
#define D_OUT   128

// ---------------------------------------------------------------------------
// Scratch (__device__ globals per allocation rules)
// ---------------------------------------------------------------------------
__device__ float g_h[(size_t)N_NODES * D_OUT];   // h = x @ W^T + b
__device__ int   g_src[N_EDGES];
__device__ int   g_dst[N_EDGES];
// W hi/lo bf16, pre-swizzled chunk images: 4 K-chunks x (128 rows x 128 bytes)
__device__ __align__(16) unsigned char g_Wh[4 * 16384];
__device__ __align__(16) unsigned char g_Wl[4 * 16384];

// ---------------------------------------------------------------------------
// helpers
// ---------------------------------------------------------------------------
__device__ __forceinline__ uint32_t smem_u32(const void* p) {
    uint32_t a;
    asm("{ .reg .u64 t; cvta.to.shared.u64 t, %1; cvt.u32.u64 %0, t; }" : "=r"(a) : "l"(p));
    return a;
}
#define SWZ(off) ((off) ^ (((off) >> 3) & 0x70))

// pack two fp32 -> bf16x2 (a -> low half, b -> high half)
__device__ __forceinline__ uint32_t pack_bf2(float a, float b) {
    uint32_t u;
    asm("cvt.rn.bf16x2.f32 %0, %1, %2;" : "=r"(u) : "f"(b), "f"(a));
    return u;
}

__device__ __forceinline__ void ldsm_x4(uint32_t* r, uint32_t addr) {
    asm volatile("ldmatrix.sync.aligned.m8n8.x4.shared.b16 {%0,%1,%2,%3}, [%4];"
                 : "=r"(r[0]), "=r"(r[1]), "=r"(r[2]), "=r"(r[3]) : "r"(addr));
}

__device__ __forceinline__ void mma_bf16(float* c, const uint32_t* a,
                                         uint32_t b0, uint32_t b1) {
    asm volatile(
        "mma.sync.aligned.m16n8k16.row.col.f32.bf16.bf16.f32 "
        "{%0,%1,%2,%3}, {%4,%5,%6,%7}, {%8,%9}, {%0,%1,%2,%3};"
        : "+f"(c[0]), "+f"(c[1]), "+f"(c[2]), "+f"(c[3])
        : "r"(a[0]), "r"(a[1]), "r"(a[2]), "r"(a[3]), "r"(b0), "r"(b1));
}

// ---------------------------------------------------------------------------
// Kernel 0: normalize index arrays (int64-or-int32 -> int32)
// ---------------------------------------------------------------------------
__global__ void convert_idx(const int* __restrict__ raw, int* __restrict__ out)
{
    __shared__ int s_is64;
    if (threadIdx.x == 0) {
        int is64 = 1;
        #pragma unroll
        for (int i = 0; i < 32; i++) {
            long long p = (long long)i * (N_EDGES / 64) * 2 + 1;
            if (raw[p] != 0) { is64 = 0; break; }
        }
        s_is64 = is64;
    }
    __syncthreads();
    const int is64 = s_is64;
    int i = blockIdx.x * blockDim.x + threadIdx.x;
    if (i < N_EDGES) {
        int v = is64 ? raw[2 * i] : raw[i];
        out[i] = min(max(v, 0), N_NODES - 1);
    }
}

// ---------------------------------------------------------------------------
// Kernel 1: convert W to hi/lo bf16, pre-swizzled chunk images (once, tiny)
// ---------------------------------------------------------------------------
__global__ void prep_W(const float* __restrict__ W)
{
    int idx = blockIdx.x * blockDim.x + threadIdx.x;
    if (idx >= 128 * 256) return;
    int n = idx >> 8;          // output row (N)
    int k = idx & 255;         // K
    float f = W[idx];
    uint32_t p = pack_bf2(f, 0.f);              // low 16 = bf16(f)
    float hf = __uint_as_float(p << 16);
    float r = f - hf;
    uint32_t pl = pack_bf2(r, 0.f);
    int c = k >> 6, kk = k & 63;
    uint32_t off = (uint32_t)(n * 128 + kk * 2);
    uint32_t sw = SWZ(off);
    *(unsigned short*)(g_Wh + c * 16384 + sw) = (unsigned short)(p & 0xFFFF);
    *(unsigned short*)(g_Wl + c * 16384 + sw) = (unsigned short)(pl & 0xFFFF);
}

// ---------------------------------------------------------------------------
// Kernel 2: bf16 mma.sync GEMM  h = x @ W^T + b  (3-term split, fp32 acc)
// Block tile M=128 x N=128, K in 4 chunks of 64. 8 warps: warpM 0..3, warpN 0..1,
// warp tile 32x64. smem: A_hi, A_lo, B_hi, B_lo each [128][64] bf16 swizzled.
// ---------------------------------------------------------------------------
#define SM_AH 0
#define SM_AL 16384
#define SM_BH 32768
#define SM_BL 49152
#define GEMM_SMEM 65536

__device__ __forceinline__ uint32_t tile_addr(uint32_t base, int row0, int k16, int lane) {
    uint32_t off = (uint32_t)((row0 + (lane & 15)) * 128 + k16 * 32 + (lane >> 4) * 16);
    return base + SWZ(off);
}

__global__ __launch_bounds__(256)
void gemm_mma(const float* __restrict__ x,
              const float* __restrict__ bias,
              float* __restrict__ hout)
{
    extern __shared__ char smem[];
    const uint32_t sb = smem_u32(smem);
    const int tid  = threadIdx.x;
    const int wid  = tid >> 5;
    const int lane = tid & 31;
    const int warpM = wid & 3;       // 0..3 -> m offset 32*warpM
    const int warpN = wid >> 2;      // 0..1 -> n offset 64*warpN

    const int m0 = blockIdx.x * 128;
    const int r  = tid >> 1;          // row within tile for A staging
    const int h2 = tid & 1;           // which 32-K half of the chunk
    const int gr = min(m0 + r, N_NODES - 1);
    const float4* xrow = (const float4*)(x + (size_t)gr * D_IN);

    float acc[2][8][4];
    #pragma unroll
    for (int i = 0; i < 2; i++)
        #pragma unroll
        for (int j = 0; j < 8; j++)
            #pragma unroll
            for (int t = 0; t < 4; t++) acc[i][j][t] = 0.f;

    #pragma unroll 1
    for (int c = 0; c < 4; c++) {
        // --- stage B chunk (pre-swizzled hi/lo, straight copy) ---
        {
            const uint4* gbh = (const uint4*)(g_Wh + c * 16384);
            const uint4* gbl = (const uint4*)(g_Wl + c * 16384);
            uint4* sbh = (uint4*)(smem + SM_BH);
            uint4* sbl = (uint4*)(smem + SM_BL);
            #pragma unroll
            for (int j = 0; j < 4; j++) {
                int idx = tid + j * 256;
                sbh[idx] = gbh[idx];
                sbl[idx] = gbl[idx];
            }
        }
        // --- stage A chunk: 32 fp32 per thread -> bf16 hi/lo, swizzled ---
        {
            const float4* s4 = xrow + ((c * 64 + h2 * 32) >> 2);
            #pragma unroll
            for (int i = 0; i < 4; i++) {
                float4 f0 = s4[2 * i];
                float4 f1 = s4[2 * i + 1];
                uint32_t u0 = pack_bf2(f0.x, f0.y);
                uint32_t u1 = pack_bf2(f0.z, f0.w);
                uint32_t u2 = pack_bf2(f1.x, f1.y);
                uint32_t u3 = pack_bf2(f1.z, f1.w);
                float a0 = f0.x - __uint_as_float(u0 << 16);
                float a1 = f0.y - __uint_as_float(u0 & 0xFFFF0000u);
                float a2 = f0.z - __uint_as_float(u1 << 16);
                float a3 = f0.w - __uint_as_float(u1 & 0xFFFF0000u);
                float a4 = f1.x - __uint_as_float(u2 << 16);
                float a5 = f1.y - __uint_as_float(u2 & 0xFFFF0000u);
                float a6 = f1.z - __uint_as_float(u3 << 16);
                float a7 = f1.w - __uint_as_float(u3 & 0xFFFF0000u);
                uint32_t off = (uint32_t)(r * 128 + h2 * 64 + i * 16);
                uint32_t sw  = SWZ(off);
                *(uint4*)(smem + SM_AH + sw) = make_uint4(u0, u1, u2, u3);
                *(uint4*)(smem + SM_AL + sw) =
                    make_uint4(pack_bf2(a0, a1), pack_bf2(a2, a3),
                               pack_bf2(a4, a5), pack_bf2(a6, a7));
            }
        }
        __syncthreads();

        // --- compute: 4 k16 steps, 3 split passes each ---
        #pragma unroll
        for (int k16 = 0; k16 < 4; k16++) {
            uint32_t Ah[2][4], Al[2][4], B[4][4];
            #pragma unroll
            for (int mf = 0; mf < 2; mf++) {
                int mrow0 = warpM * 32 + mf * 16;
                ldsm_x4(Ah[mf], tile_addr(sb + SM_AH, mrow0, k16, lane));
                ldsm_x4(Al[mf], tile_addr(sb + SM_AL, mrow0, k16, lane));
            }
            // pass 1+2: B = W_hi
            #pragma unroll
            for (int j = 0; j < 4; j++)
                ldsm_x4(B[j], tile_addr(sb + SM_BH, warpN * 64 + j * 16, k16, lane));
            #pragma unroll
            for (int mf = 0; mf < 2; mf++)
                #pragma unroll
                for (int j = 0; j < 4; j++) {
                    mma_bf16(acc[mf][2 * j],     Ah[mf], B[j][0], B[j][2]);
                    mma_bf16(acc[mf][2 * j + 1], Ah[mf], B[j][1], B[j][3]);
                    mma_bf16(acc[mf][2 * j],     Al[mf], B[j][0], B[j][2]);
                    mma_bf16(acc[mf][2 * j + 1], Al[mf], B[j][1], B[j][3]);
                }
            // pass 3: B = W_lo
            #pragma unroll
            for (int j = 0; j < 4; j++)
                ldsm_x4(B[j], tile_addr(sb + SM_BL, warpN * 64 + j * 16, k16, lane));
            #pragma unroll
            for (int mf = 0; mf < 2; mf++)
                #pragma unroll
                for (int j = 0; j < 4; j++) {
                    mma_bf16(acc[mf][2 * j],     Ah[mf], B[j][0], B[j][2]);
                    mma_bf16(acc[mf][2 * j + 1], Ah[mf], B[j][1], B[j][3]);
                }
        }
        __syncthreads();
    }

    // --- epilogue: registers -> gmem with bias (no transpose needed) ---
    const int g  = lane >> 2;
    const int tg = lane & 3;
    #pragma unroll
    for (int mf = 0; mf < 2; mf++) {
        #pragma unroll
        for (int nf = 0; nf < 8; nf++) {
            int col = warpN * 64 + nf * 8 + tg * 2;
            float b0 = bias[col], b1 = bias[col + 1];
            int row = m0 + warpM * 32 + mf * 16 + g;
            if (row < N_NODES) {
                float2 v = make_float2(acc[mf][nf][0] + b0, acc[mf][nf][1] + b1);
                *(float2*)&hout[(size_t)row * D_OUT + col] = v;
            }
            if (row + 8 < N_NODES) {
                float2 v = make_float2(acc[mf][nf][2] + b0, acc[mf][nf][3] + b1);
                *(float2*)&hout[(size_t)(row + 8) * D_OUT + col] = v;
            }
        }
    }
}

// ---------------------------------------------------------------------------
// Kernel 3: zero the output
// ---------------------------------------------------------------------------
__global__ void zero_out(float4* __restrict__ out, int n4)
{
    int i = blockIdx.x * blockDim.x + threadIdx.x;
    if (i < n4) out[i] = make_float4(0.f, 0.f, 0.f, 0.f);
}

// ---------------------------------------------------------------------------
// Kernel 4: edge gather + segment-sum scatter (dst sorted)
// ---------------------------------------------------------------------------
#define EPB 256

__global__ __launch_bounds__(128)
void edge_scatter(const int* __restrict__ src,
                  const int* __restrict__ dst,
                  const float* __restrict__ w,
                  const float* __restrict__ h,
                  float* __restrict__ out)
{
    __shared__ int   s_src[EPB];
    __shared__ int   s_dst[EPB];
    __shared__ float s_w[EPB];

    const int e0 = blockIdx.x * EPB;
    if (e0 >= N_EDGES) return;
    const int cnt = min(EPB, N_EDGES - e0);
    const int tid = threadIdx.x;

    for (int i = tid; i < cnt; i += 128) {
        s_src[i] = src[e0 + i];
        s_dst[i] = dst[e0 + i];
        s_w[i]   = w[e0 + i];
    }
    __syncthreads();

    const int c = tid;
    float acc = 0.f;
    int cur = s_dst[0];

    for (int j = 0; j < cnt; j++) {
        int d = s_dst[j];
        if (d != cur) {
            atomicAdd(&out[(size_t)cur * D_OUT + c], acc);
            acc = 0.f;
            cur = d;
        }
        acc = fmaf(s_w[j], __ldg(&h[(size_t)s_src[j] * D_OUT + c]), acc);
    }
    atomicAdd(&out[(size_t)cur * D_OUT + c], acc);
}

// ---------------------------------------------------------------------------
// launch
// ---------------------------------------------------------------------------
extern "C" void kernel_launch(void* const* d_in, const int* in_sizes, int n_in,
                              void* d_out, int out_size)
{
    const float* x    = (const float*)d_in[0];
    const int*   srcR = (const int*)d_in[1];
    const int*   dstR = (const int*)d_in[2];
    const float* w    = (const float*)d_in[3];
    const float* W    = (const float*)d_in[4];
    const float* b    = (const float*)d_in[5];
    float*       out  = (float*)d_out;

    float* h = nullptr;
    int *srcI = nullptr, *dstI = nullptr;
    cudaGetSymbolAddress((void**)&h, g_h);
    cudaGetSymbolAddress((void**)&srcI, g_src);
    cudaGetSymbolAddress((void**)&dstI, g_dst);

    cudaFuncSetAttribute(gemm_mma, cudaFuncAttributeMaxDynamicSharedMemorySize, GEMM_SMEM);

    convert_idx<<<(N_EDGES + 255) / 256, 256>>>(srcR, srcI);
    convert_idx<<<(N_EDGES + 255) / 256, 256>>>(dstR, dstI);

    prep_W<<<128, 256>>>(W);
    gemm_mma<<<(N_NODES + 127) / 128, 256, GEMM_SMEM>>>(x, b, h);

    int n4 = (N_NODES * D_OUT) / 4;
    zero_out<<<(n4 + 255) / 256, 256>>>((float4*)out, n4);

    edge_scatter<<<(N_EDGES + EPB - 1) / EPB, 128>>>(srcI, dstI, w, h, out);
}

// round 6
// speedup vs baseline: 1.9121x; 1.5393x over previous
#include <cuda_runtime.h>
#include <cuda_bf16.h>
#include <cstdint>

#define N_NODES 100000
#define N_EDGES 1600000
#define D_IN    256
#define D_OUT   128

// ---------------------------------------------------------------------------
// Scratch (__device__ globals per allocation rules)
// ---------------------------------------------------------------------------
__device__ float g_h[(size_t)N_NODES * D_OUT];   // h = x @ W^T + b
// W hi/lo bf16, pre-swizzled chunk images: 4 K-chunks x (128 rows x 128 bytes)
__device__ __align__(16) unsigned char g_Wh[4 * 16384];
__device__ __align__(16) unsigned char g_Wl[4 * 16384];

// ---------------------------------------------------------------------------
// helpers
// ---------------------------------------------------------------------------
__device__ __forceinline__ uint32_t smem_u32(const void* p) {
    uint32_t a;
    asm("{ .reg .u64 t; cvta.to.shared.u64 t, %1; cvt.u32.u64 %0, t; }" : "=r"(a) : "l"(p));
    return a;
}
#define SWZ(off) ((off) ^ (((off) >> 3) & 0x70))

// pack two fp32 -> bf16x2 (a -> low half, b -> high half)
__device__ __forceinline__ uint32_t pack_bf2(float a, float b) {
    uint32_t u;
    asm("cvt.rn.bf16x2.f32 %0, %1, %2;" : "=r"(u) : "f"(b), "f"(a));
    return u;
}

__device__ __forceinline__ void ldsm_x4(uint32_t* r, uint32_t addr) {
    asm volatile("ldmatrix.sync.aligned.m8n8.x4.shared.b16 {%0,%1,%2,%3}, [%4];"
                 : "=r"(r[0]), "=r"(r[1]), "=r"(r[2]), "=r"(r[3]) : "r"(addr));
}

__device__ __forceinline__ void mma_bf16(float* c, const uint32_t* a,
                                         uint32_t b0, uint32_t b1) {
    asm volatile(
        "mma.sync.aligned.m16n8k16.row.col.f32.bf16.bf16.f32 "
        "{%0,%1,%2,%3}, {%4,%5,%6,%7}, {%8,%9}, {%0,%1,%2,%3};"
        : "+f"(c[0]), "+f"(c[1]), "+f"(c[2]), "+f"(c[3])
        : "r"(a[0]), "r"(a[1]), "r"(a[2]), "r"(a[3]), "r"(b0), "r"(b1));
}

__device__ __forceinline__ void cp16(uint32_t d, const void* s) {
    asm volatile("cp.async.cg.shared.global [%0], [%1], 16;" :: "r"(d), "l"(s));
}
#define CP_COMMIT() asm volatile("cp.async.commit_group;" ::: "memory")
#define CP_WAIT0()  asm volatile("cp.async.wait_group 0;" ::: "memory")

// ---------------------------------------------------------------------------
// Kernel 1: convert W to hi/lo bf16, pre-swizzled chunk images (once, tiny)
// ---------------------------------------------------------------------------
__global__ void prep_W(const float* __restrict__ W)
{
    int idx = blockIdx.x * blockDim.x + threadIdx.x;
    if (idx >= 128 * 256) return;
    int n = idx >> 8;          // output row (N)
    int k = idx & 255;         // K
    float f = W[idx];
    uint32_t p = pack_bf2(f, 0.f);              // low 16 = bf16(f)
    float hf = __uint_as_float(p << 16);
    float r = f - hf;
    uint32_t pl = pack_bf2(r, 0.f);
    int c = k >> 6, kk = k & 63;
    uint32_t off = (uint32_t)(n * 128 + kk * 2);
    uint32_t sw = SWZ(off);
    *(unsigned short*)(g_Wh + c * 16384 + sw) = (unsigned short)(p & 0xFFFF);
    *(unsigned short*)(g_Wl + c * 16384 + sw) = (unsigned short)(pl & 0xFFFF);
}

// ---------------------------------------------------------------------------
// Kernel 2: bf16 mma.sync GEMM  h = x @ W^T + b  (3-term split, fp32 acc)
// Block tile M=128 x N=128, K in 4 chunks of 64. 8 warps: warpM 0..3, warpN 0..1.
// 2 CTAs/SM (128-reg cap); B staged via cp.async; j-major MMA loop keeps
// only one B fragment live.
// ---------------------------------------------------------------------------
#define SM_AH 0
#define SM_AL 16384
#define SM_BH 32768
#define SM_BL 49152
#define GEMM_SMEM 65536

__device__ __forceinline__ uint32_t tile_addr(uint32_t base, int row0, int k16, int lane) {
    uint32_t off = (uint32_t)((row0 + (lane & 15)) * 128 + k16 * 32 + (lane >> 4) * 16);
    return base + SWZ(off);
}

__global__ __launch_bounds__(256, 2)
void gemm_mma(const float* __restrict__ x,
              const float* __restrict__ bias,
              float* __restrict__ hout)
{
    extern __shared__ char smem[];
    const uint32_t sb = smem_u32(smem);
    const int tid  = threadIdx.x;
    const int wid  = tid >> 5;
    const int lane = tid & 31;
    const int warpM = wid & 3;       // 0..3 -> m offset 32*warpM
    const int warpN = wid >> 2;      // 0..1 -> n offset 64*warpN

    const int m0 = blockIdx.x * 128;
    const int r  = tid >> 1;          // row within tile for A staging
    const int h2 = tid & 1;           // which 32-K half of the chunk
    const int gr = min(m0 + r, N_NODES - 1);
    const float4* xrow = (const float4*)(x + (size_t)gr * D_IN);

    float acc[2][8][4];
    #pragma unroll
    for (int i = 0; i < 2; i++)
        #pragma unroll
        for (int j = 0; j < 8; j++)
            #pragma unroll
            for (int t = 0; t < 4; t++) acc[i][j][t] = 0.f;

    #pragma unroll 1
    for (int c = 0; c < 4; c++) {
        // --- B chunk via cp.async (pre-swizzled hi/lo, straight copy) ---
        {
            const unsigned char* gbh = g_Wh + c * 16384;
            const unsigned char* gbl = g_Wl + c * 16384;
            #pragma unroll
            for (int j = 0; j < 4; j++) {
                uint32_t boff = (uint32_t)(tid + j * 256) * 16;
                cp16(sb + SM_BH + boff, gbh + boff);
                cp16(sb + SM_BL + boff, gbl + boff);
            }
            CP_COMMIT();
        }
        // --- stage A chunk: 32 fp32 per thread -> bf16 hi/lo, swizzled ---
        {
            const float4* s4 = xrow + ((c * 64 + h2 * 32) >> 2);
            #pragma unroll
            for (int i = 0; i < 4; i++) {
                float4 f0 = s4[2 * i];
                float4 f1 = s4[2 * i + 1];
                uint32_t u0 = pack_bf2(f0.x, f0.y);
                uint32_t u1 = pack_bf2(f0.z, f0.w);
                uint32_t u2 = pack_bf2(f1.x, f1.y);
                uint32_t u3 = pack_bf2(f1.z, f1.w);
                float a0 = f0.x - __uint_as_float(u0 << 16);
                float a1 = f0.y - __uint_as_float(u0 & 0xFFFF0000u);
                float a2 = f0.z - __uint_as_float(u1 << 16);
                float a3 = f0.w - __uint_as_float(u1 & 0xFFFF0000u);
                float a4 = f1.x - __uint_as_float(u2 << 16);
                float a5 = f1.y - __uint_as_float(u2 & 0xFFFF0000u);
                float a6 = f1.z - __uint_as_float(u3 << 16);
                float a7 = f1.w - __uint_as_float(u3 & 0xFFFF0000u);
                uint32_t off = (uint32_t)(r * 128 + h2 * 64 + i * 16);
                uint32_t sw  = SWZ(off);
                *(uint4*)(smem + SM_AH + sw) = make_uint4(u0, u1, u2, u3);
                *(uint4*)(smem + SM_AL + sw) =
                    make_uint4(pack_bf2(a0, a1), pack_bf2(a2, a3),
                               pack_bf2(a4, a5), pack_bf2(a6, a7));
            }
        }
        CP_WAIT0();
        __syncthreads();

        // --- compute: 4 k16 steps; j-major so only one B frag is live ---
        #pragma unroll
        for (int k16 = 0; k16 < 4; k16++) {
            uint32_t Ah[2][4], Al[2][4];
            #pragma unroll
            for (int mf = 0; mf < 2; mf++) {
                int mrow0 = warpM * 32 + mf * 16;
                ldsm_x4(Ah[mf], tile_addr(sb + SM_AH, mrow0, k16, lane));
                ldsm_x4(Al[mf], tile_addr(sb + SM_AL, mrow0, k16, lane));
            }
            #pragma unroll
            for (int j = 0; j < 4; j++) {
                uint32_t B[4];
                ldsm_x4(B, tile_addr(sb + SM_BH, warpN * 64 + j * 16, k16, lane));
                #pragma unroll
                for (int mf = 0; mf < 2; mf++) {
                    mma_bf16(acc[mf][2 * j],     Ah[mf], B[0], B[2]);
                    mma_bf16(acc[mf][2 * j + 1], Ah[mf], B[1], B[3]);
                    mma_bf16(acc[mf][2 * j],     Al[mf], B[0], B[2]);
                    mma_bf16(acc[mf][2 * j + 1], Al[mf], B[1], B[3]);
                }
            }
            #pragma unroll
            for (int j = 0; j < 4; j++) {
                uint32_t B[4];
                ldsm_x4(B, tile_addr(sb + SM_BL, warpN * 64 + j * 16, k16, lane));
                #pragma unroll
                for (int mf = 0; mf < 2; mf++) {
                    mma_bf16(acc[mf][2 * j],     Ah[mf], B[0], B[2]);
                    mma_bf16(acc[mf][2 * j + 1], Ah[mf], B[1], B[3]);
                }
            }
        }
        __syncthreads();
    }

    // --- epilogue: registers -> gmem with bias (no transpose needed) ---
    const int g  = lane >> 2;
    const int tg = lane & 3;
    #pragma unroll
    for (int mf = 0; mf < 2; mf++) {
        #pragma unroll
        for (int nf = 0; nf < 8; nf++) {
            int col = warpN * 64 + nf * 8 + tg * 2;
            float b0 = bias[col], b1 = bias[col + 1];
            int row = m0 + warpM * 32 + mf * 16 + g;
            if (row < N_NODES) {
                float2 v = make_float2(acc[mf][nf][0] + b0, acc[mf][nf][1] + b1);
                *(float2*)&hout[(size_t)row * D_OUT + col] = v;
            }
            if (row + 8 < N_NODES) {
                float2 v = make_float2(acc[mf][nf][2] + b0, acc[mf][nf][3] + b1);
                *(float2*)&hout[(size_t)(row + 8) * D_OUT + col] = v;
            }
        }
    }
}

// ---------------------------------------------------------------------------
// Kernel 3: zero the output
// ---------------------------------------------------------------------------
__global__ void zero_out(float4* __restrict__ out, int n4)
{
    int i = blockIdx.x * blockDim.x + threadIdx.x;
    if (i < n4) out[i] = make_float4(0.f, 0.f, 0.f, 0.f);
}

// ---------------------------------------------------------------------------
// Kernel 4: edge gather + segment-sum scatter (dst sorted).
// 512 edges/block; 4 warps each own 128 edges; each lane owns 4 channels
// (float4) so one warp gathers a full 512B h-row per edge, coalesced.
// Index dtype (int64 vs int32) auto-detected per block; values clamped.
// ---------------------------------------------------------------------------
#define EPB 512
#define EPW (EPB / 4)

__global__ __launch_bounds__(128)
void edge_scatter(const void* __restrict__ srcRaw,
                  const void* __restrict__ dstRaw,
                  const float* __restrict__ w,
                  const float* __restrict__ h,
                  float* __restrict__ out)
{
    __shared__ int   s_src[EPB];
    __shared__ int   s_dst[EPB];
    __shared__ float s_w[EPB];
    __shared__ int   s_flags;

    const int tid = threadIdx.x;
    const int e0  = blockIdx.x * EPB;

    if (tid == 0) {
        const int* a32 = (const int*)srcRaw;
        const int* b32 = (const int*)dstRaw;
        int fs = 1, fd = 1;
        #pragma unroll
        for (int i = 0; i < 8; i++) {
            int k = (i + 1) * (N_EDGES / 20);   // k <= 640000, 2k+1 < N_EDGES
            if (a32[2 * k + 1] != 0) fs = 0;
            if (b32[2 * k + 1] != 0) fd = 0;
        }
        s_flags = fs | (fd << 1);
    }
    __syncthreads();
    const int is64s = s_flags & 1;
    const int is64d = (s_flags >> 1) & 1;

    const long long* sll = (const long long*)srcRaw;
    const long long* dll = (const long long*)dstRaw;
    const int*       s32 = (const int*)srcRaw;
    const int*       d32 = (const int*)dstRaw;

    #pragma unroll
    for (int i = tid; i < EPB; i += 128) {
        int sv = is64s ? (int)sll[e0 + i] : s32[e0 + i];
        int dv = is64d ? (int)dll[e0 + i] : d32[e0 + i];
        s_src[i] = min(max(sv, 0), N_NODES - 1);
        s_dst[i] = min(max(dv, 0), N_NODES - 1);
        s_w[i]   = w[e0 + i];
    }
    __syncthreads();

    const int g    = tid >> 5;
    const int lane = tid & 31;
    const int j0   = g * EPW;
    const float4* h4 = (const float4*)h;

    float4 acc = make_float4(0.f, 0.f, 0.f, 0.f);
    int cur = s_dst[j0];

    for (int j = j0; j < j0 + EPW; j++) {
        int d = s_dst[j];
        if (d != cur) {
            float* p = &out[(size_t)cur * D_OUT + lane * 4];
            atomicAdd(p + 0, acc.x); atomicAdd(p + 1, acc.y);
            atomicAdd(p + 2, acc.z); atomicAdd(p + 3, acc.w);
            acc = make_float4(0.f, 0.f, 0.f, 0.f);
            cur = d;
        }
        float4 hv = __ldg(&h4[(size_t)s_src[j] * 32 + lane]);
        float wv = s_w[j];
        acc.x = fmaf(wv, hv.x, acc.x);
        acc.y = fmaf(wv, hv.y, acc.y);
        acc.z = fmaf(wv, hv.z, acc.z);
        acc.w = fmaf(wv, hv.w, acc.w);
    }
    float* p = &out[(size_t)cur * D_OUT + lane * 4];
    atomicAdd(p + 0, acc.x); atomicAdd(p + 1, acc.y);
    atomicAdd(p + 2, acc.z); atomicAdd(p + 3, acc.w);
}

// ---------------------------------------------------------------------------
// launch
// ---------------------------------------------------------------------------
extern "C" void kernel_launch(void* const* d_in, const int* in_sizes, int n_in,
                              void* d_out, int out_size)
{
    const float* x    = (const float*)d_in[0];
    const void*  srcR = d_in[1];
    const void*  dstR = d_in[2];
    const float* w    = (const float*)d_in[3];
    const float* W    = (const float*)d_in[4];
    const float* b    = (const float*)d_in[5];
    float*       out  = (float*)d_out;

    float* h = nullptr;
    cudaGetSymbolAddress((void**)&h, g_h);

    cudaFuncSetAttribute(gemm_mma, cudaFuncAttributeMaxDynamicSharedMemorySize, GEMM_SMEM);

    prep_W<<<128, 256>>>(W);
    gemm_mma<<<(N_NODES + 127) / 128, 256, GEMM_SMEM>>>(x, b, h);

    int n4 = (N_NODES * D_OUT) / 4;
    zero_out<<<(n4 + 255) / 256, 256>>>((float4*)out, n4);

    edge_scatter<<<N_EDGES / EPB, 128>>>(srcR, dstR, w, h, out);
}